// round 10
// baseline (speedup 1.0000x reference)
#include <cuda_runtime.h>
#include <cstdint>

#define HH 128
#define NPAD 100096          // = 782*128
#define EMAX 1600000
#define NTH 256
#define SCAN_B 512

// ---------------- scratch ----------------
__device__ float g_xp [NPAD * HH];
__device__ float g_acc[NPAD * HH];     // MEAN-aggregated features
__device__ float g_h  [NPAD * HH];
__device__ float g_xp0[NPAD * 2];
__device__ int   g_deg [NPAD];
__device__ int   g_off [NPAD + 1];
__device__ int   g_cur [NPAD];
__device__ int   g_srcs[EMAX];
__device__ int   g_bsum [4096];
__device__ int   g_bsumx[4096];

__device__ __forceinline__ float warp_sum(float v) {
#pragma unroll
    for (int o = 16; o > 0; o >>= 1) v += __shfl_xor_sync(0xffffffffu, v, o);
    return v;
}
__device__ __forceinline__ float quad_sum(float v) {
    v += __shfl_xor_sync(0xffffffffu, v, 1);
    v += __shfl_xor_sync(0xffffffffu, v, 2);
    return v;
}
__device__ __forceinline__ uint32_t f2tf(float f) {
    uint32_t r;
    asm("cvt.rna.tf32.f32 %0, %1;" : "=r"(r) : "f"(f));
    return r;
}

#define MMA_TF32(d, a0v, a1v, a2v, a3v, b0v, b1v)                                \
    asm volatile(                                                                \
        "mma.sync.aligned.m16n8k8.row.col.f32.tf32.tf32.f32 "                    \
        "{%0,%1,%2,%3}, {%4,%5,%6,%7}, {%8,%9}, {%0,%1,%2,%3};"                  \
        : "+f"(d[0]), "+f"(d[1]), "+f"(d[2]), "+f"(d[3])                         \
        : "r"(a0v), "r"(a1v), "r"(a2v), "r"(a3v), "r"(b0v), "r"(b1v))

// ================= CSR build =================
__global__ void k_hist(const int* __restrict__ ei, int E) {
    int e = blockIdx.x * blockDim.x + threadIdx.x;
    if (e >= E) return;
    atomicAdd(&g_deg[ei[E + e]], 1);
}
__global__ void __launch_bounds__(SCAN_B) k_scan1(int n) {
    __shared__ int sm[SCAN_B];
    int t = threadIdx.x;
    int idx = blockIdx.x * SCAN_B + t;
    int v = (idx < n) ? g_deg[idx] : 0;
    sm[t] = v;
    __syncthreads();
#pragma unroll
    for (int off = 1; off < SCAN_B; off <<= 1) {
        int add = (t >= off) ? sm[t - off] : 0;
        __syncthreads();
        sm[t] += add;
        __syncthreads();
    }
    if (idx < n) g_off[idx] = sm[t] - v;
    if (t == SCAN_B - 1) g_bsum[blockIdx.x] = sm[t];
}
__global__ void __launch_bounds__(1024) k_scan2(int nb) {
    __shared__ int sm[1024];
    int t = threadIdx.x;
    int v = (t < nb) ? g_bsum[t] : 0;
    sm[t] = v;
    __syncthreads();
#pragma unroll
    for (int off = 1; off < 1024; off <<= 1) {
        int add = (t >= off) ? sm[t - off] : 0;
        __syncthreads();
        sm[t] += add;
        __syncthreads();
    }
    if (t < nb) g_bsumx[t] = sm[t] - v;
}
__global__ void k_scan3(int n, int E) {
    int idx = blockIdx.x * blockDim.x + threadIdx.x;
    if (idx == 0) g_off[n] = E;
    if (idx >= n) return;
    int o = g_off[idx] + g_bsumx[idx / SCAN_B];
    g_off[idx] = o;
    g_cur[idx] = o;
}
__global__ void k_scatter(const int* __restrict__ ei, int E) {
    int e = blockIdx.x * blockDim.x + threadIdx.x;
    if (e >= E) return;
    int s = ei[e], d = ei[E + e];
    int pos = atomicAdd(&g_cur[d], 1);
    g_srcs[pos] = s;
}

// ================= layer 0 =================
__global__ void k_l0(const float* __restrict__ x, const float* __restrict__ Wp,
                     const float* __restrict__ bp, int n) {
    int i = blockIdx.x * blockDim.x + threadIdx.x;
    if (i >= n) return;
    float x0 = x[2 * i], x1 = x[2 * i + 1];
    float a = fmaxf(fmaf(x0, Wp[0], fmaf(x1, Wp[2], bp[0])), 0.f);
    float b = fmaxf(fmaf(x0, Wp[1], fmaf(x1, Wp[3], bp[1])), 0.f);
    g_xp0[2 * i] = a;
    g_xp0[2 * i + 1] = b;
}

__global__ void __launch_bounds__(256) k_combine0(int n, const float* __restrict__ Wl,
        const float* __restrict__ bl, const float* __restrict__ Wr,
        const float* __restrict__ lnw, const float* __restrict__ lnb) {
    int node = (blockIdx.x * 256 + threadIdx.x) >> 5;
    int lane = threadIdx.x & 31;
    if (node >= n) return;
    int beg = g_off[node], end = g_off[node + 1];
    float m0 = 0.f, m1 = 0.f;
    for (int j = beg + lane; j < end; j += 32) {
        int s = __ldg(&g_srcs[j]);
        float2 v = *(const float2*)&g_xp0[2 * s];
        m0 += v.x; m1 += v.y;
    }
    m0 = warp_sum(m0); m1 = warp_sum(m1);
    float inv = 1.f / fmaxf((float)(end - beg), 1.f);
    m0 *= inv; m1 *= inv;
    float p0 = g_xp0[2 * node], p1 = g_xp0[2 * node + 1];
    float v[4]; float s = 0.f;
#pragma unroll
    for (int k = 0; k < 4; k++) {
        int c = lane + 32 * k;
        v[k] = fmaf(m0, Wl[c], fmaf(m1, Wl[HH + c],
               fmaf(p0, Wr[c], fmaf(p1, Wr[HH + c], bl[c]))));
        s += v[k];
    }
    s = warp_sum(s);
    float mu = s * (1.f / HH);
    float q = 0.f;
#pragma unroll
    for (int k = 0; k < 4; k++) { v[k] -= mu; q += v[k] * v[k]; }
    q = warp_sum(q);
    float rstd = rsqrtf(q * (1.f / HH) + 1e-5f);
    size_t base = (size_t)node * HH;
#pragma unroll
    for (int k = 0; k < 4; k++) {
        int c = lane + 32 * k;
        g_h[base + c] = v[k] * rstd * lnw[c] + lnb[c];
    }
}

// ================= heavy aggregation: CSR gather-reduce, warp per node =================
__global__ void __launch_bounds__(256) k_gagg(int n) {
    int node = (blockIdx.x * 256 + threadIdx.x) >> 5;
    int lane = threadIdx.x & 31;
    if (node >= n) return;
    int beg = g_off[node], end = g_off[node + 1];
    float4 a0 = make_float4(0.f, 0.f, 0.f, 0.f);
    float4 a1 = make_float4(0.f, 0.f, 0.f, 0.f);
    int j = beg;
    for (; j + 4 <= end; j += 4) {
        int s0 = __ldg(&g_srcs[j]);
        int s1 = __ldg(&g_srcs[j + 1]);
        int s2 = __ldg(&g_srcs[j + 2]);
        int s3 = __ldg(&g_srcs[j + 3]);
        float4 v0 = *(const float4*)&g_xp[(size_t)s0 * HH + lane * 4];
        float4 v1 = *(const float4*)&g_xp[(size_t)s1 * HH + lane * 4];
        float4 v2 = *(const float4*)&g_xp[(size_t)s2 * HH + lane * 4];
        float4 v3 = *(const float4*)&g_xp[(size_t)s3 * HH + lane * 4];
        a0.x += v0.x + v1.x; a0.y += v0.y + v1.y;
        a0.z += v0.z + v1.z; a0.w += v0.w + v1.w;
        a1.x += v2.x + v3.x; a1.y += v2.y + v3.y;
        a1.z += v2.z + v3.z; a1.w += v2.w + v3.w;
    }
    for (; j < end; j++) {
        int s0 = __ldg(&g_srcs[j]);
        float4 v0 = *(const float4*)&g_xp[(size_t)s0 * HH + lane * 4];
        a0.x += v0.x; a0.y += v0.y; a0.z += v0.z; a0.w += v0.w;
    }
    float inv = 1.f / fmaxf((float)(end - beg), 1.f);
    float4 a;
    a.x = (a0.x + a1.x) * inv; a.y = (a0.y + a1.y) * inv;
    a.z = (a0.z + a1.z) * inv; a.w = (a0.w + a1.w) * inv;
    *(float4*)&g_acc[(size_t)node * HH + lane * 4] = a;
}

// =================== 3xTF32 MMA GEMM core, 4x2 warp grid ===================
// CTA tile 128x128, 8 warps as 4(M) x 2(N): warp tile 32x64.
// hi/lo split done once at staging; smem holds interleaved (hi,lo) pairs.
// As[2][128][24]: row=m, col=2k+{0,1}; Ws[2][8][264]: row=k, col=2n+{0,1}.
// Per warp per k8: A = 8 LDS.64 (2 m-tiles), B = 16 LDS.64 (8 n-tiles,
// each feeding BOTH m-tiles -> 48 MMAs). 33% less LDS than 1x8 layout.

#define GEMM_DECLS                                                            \
    const int t = threadIdx.x;                                                \
    const int warp = t >> 5, lane = t & 31;                                   \
    const int g = lane >> 2, q = lane & 3;                                    \
    const int mrow = (warp & 3) * 32;                                         \
    const int n0 = (warp >> 2) * 64;                                          \
    const int nhalf = warp >> 2;                                              \
    const int ar = t >> 1, akb = (t & 1) * 4;                                 \
    const int wr = t >> 5, wcol = (t & 31) * 4;                               \
    float4 pa, pw;                                                            \
    float c[2][8][4];                                                         \
    _Pragma("unroll")                                                         \
    for (int mt = 0; mt < 2; mt++)                                            \
        _Pragma("unroll")                                                     \
        for (int j = 0; j < 8; j++)                                           \
            _Pragma("unroll")                                                 \
            for (int u = 0; u < 4; u++) c[mt][j][u] = 0.f;

// split float4 v into (hi,lo) pairs and store 32B at dst
#define SPLIT_STS(v, dst)                                                     \
    {                                                                         \
        float h0 = __uint_as_float(f2tf(v.x));                                \
        float h1 = __uint_as_float(f2tf(v.y));                                \
        float h2 = __uint_as_float(f2tf(v.z));                                \
        float h3 = __uint_as_float(f2tf(v.w));                                \
        float4 o0, o1;                                                        \
        o0.x = h0; o0.y = v.x - h0; o0.z = h1; o0.w = v.y - h1;               \
        o1.x = h2; o1.y = v.z - h2; o1.z = h3; o1.w = v.w - h3;               \
        ((float4*)(dst))[0] = o0; ((float4*)(dst))[1] = o1;                   \
    }

#define STAGE(buf)                                                            \
    {                                                                         \
        SPLIT_STS(pa, &As[buf][ar][2 * akb]);                                 \
        SPLIT_STS(pw, &Ws[buf][wr][2 * wcol]);                                \
    }

#define GEMM_COMPUTE(cur)                                                     \
    {                                                                         \
        uint32_t ah[2][4], al[2][4];                                          \
        _Pragma("unroll")                                                     \
        for (int mt = 0; mt < 2; mt++) {                                      \
            int r = mrow + mt * 16;                                           \
            float2 x0 = *(const float2*)&As[cur][r + g][2 * q];               \
            float2 x1 = *(const float2*)&As[cur][r + g + 8][2 * q];           \
            float2 x2 = *(const float2*)&As[cur][r + g][2 * (q + 4)];         \
            float2 x3 = *(const float2*)&As[cur][r + g + 8][2 * (q + 4)];     \
            ah[mt][0] = __float_as_uint(x0.x); al[mt][0] = __float_as_uint(x0.y); \
            ah[mt][1] = __float_as_uint(x1.x); al[mt][1] = __float_as_uint(x1.y); \
            ah[mt][2] = __float_as_uint(x2.x); al[mt][2] = __float_as_uint(x2.y); \
            ah[mt][3] = __float_as_uint(x3.x); al[mt][3] = __float_as_uint(x3.y); \
        }                                                                     \
        _Pragma("unroll")                                                     \
        for (int j = 0; j < 8; j++) {                                         \
            float2 b0 = *(const float2*)&Ws[cur][q][2 * (n0 + 8 * j + g)];    \
            float2 b1 = *(const float2*)&Ws[cur][q + 4][2 * (n0 + 8 * j + g)];\
            uint32_t bh0 = __float_as_uint(b0.x), bl0 = __float_as_uint(b0.y);\
            uint32_t bh1 = __float_as_uint(b1.x), bl1 = __float_as_uint(b1.y);\
            MMA_TF32(c[0][j], ah[0][0], ah[0][1], ah[0][2], ah[0][3], bl0, bl1); \
            MMA_TF32(c[0][j], al[0][0], al[0][1], al[0][2], al[0][3], bh0, bh1); \
            MMA_TF32(c[0][j], ah[0][0], ah[0][1], ah[0][2], ah[0][3], bh0, bh1); \
            MMA_TF32(c[1][j], ah[1][0], ah[1][1], ah[1][2], ah[1][3], bl0, bl1); \
            MMA_TF32(c[1][j], al[1][0], al[1][1], al[1][2], al[1][3], bh0, bh1); \
            MMA_TF32(c[1][j], ah[1][0], ah[1][1], ah[1][2], ah[1][3], bh0, bh1); \
        }                                                                     \
    }

// ---------------- proj GEMM: xp = relu(h @ Wp + bp) ----------------
__global__ void __launch_bounds__(NTH, 2) k_proj(const float* __restrict__ W,
                                                 const float* __restrict__ bias) {
    __shared__ float As[2][128][24];
    __shared__ float Ws[2][8][264];
    GEMM_DECLS
    const int row0 = blockIdx.x * 128;
    const float* Arow = &g_h[(size_t)(row0 + ar) * HH];

    pa = *(const float4*)(Arow + akb);
    pw = *(const float4*)&W[(size_t)wr * HH + wcol];
    STAGE(0);

    const int NT = HH / 8;  // 16
#pragma unroll 2
    for (int it = 0; it < NT; it++) {
        int cur = it & 1;
        __syncthreads();
        if (it + 1 < NT) {
            int k0 = (it + 1) * 8;
            pa = *(const float4*)(Arow + k0 + akb);
            pw = *(const float4*)&W[(size_t)(k0 + wr) * HH + wcol];
        }
        GEMM_COMPUTE(cur)
        if (it + 1 < NT) STAGE(cur ^ 1);
    }

#pragma unroll
    for (int mt = 0; mt < 2; mt++) {
        int r0 = row0 + mrow + mt * 16 + g, r1 = r0 + 8;
#pragma unroll
        for (int j = 0; j < 8; j++) {
            int jc = n0 + 8 * j + 2 * q;
            float2 bv = *(const float2*)&bias[jc];
            float2 o0, o1;
            o0.x = fmaxf(c[mt][j][0] + bv.x, 0.f); o0.y = fmaxf(c[mt][j][1] + bv.y, 0.f);
            o1.x = fmaxf(c[mt][j][2] + bv.x, 0.f); o1.y = fmaxf(c[mt][j][3] + bv.y, 0.f);
            *(float2*)&g_xp[(size_t)r0 * HH + jc] = o0;
            *(float2*)&g_xp[(size_t)r1 * HH + jc] = o1;
        }
    }
}

// ---------------- combine GEMM (K=256: mean | xp) + fused LN ----------------
__global__ void __launch_bounds__(NTH, 2) k_combine(const float* __restrict__ Wl,
        const float* __restrict__ Wr, const float* __restrict__ bl,
        const float* __restrict__ lnw, const float* __restrict__ lnb) {
    __shared__ float As[2][128][24];
    __shared__ float Ws[2][8][264];
    __shared__ float pbuf[128][2];
    __shared__ float vbuf[128][2];
    GEMM_DECLS
    const int row0 = blockIdx.x * 128;
    const float* Aa = &g_acc[(size_t)(row0 + ar) * HH];
    const float* Ax = &g_xp[(size_t)(row0 + ar) * HH];

    pa = *(const float4*)(Aa + akb);
    pw = *(const float4*)&Wl[(size_t)wr * HH + wcol];
    STAGE(0);

    const int NT = 32;  // K=256 / 8
#pragma unroll 2
    for (int it = 0; it < NT; it++) {
        int cur = it & 1;
        __syncthreads();
        if (it + 1 < NT) {
            int nx = it + 1;
            const float* Ap;
            const float* Wn;
            if (nx < 16) { Ap = Aa + nx * 8; Wn = Wl + (size_t)nx * 8 * HH; }
            else         { Ap = Ax + (nx - 16) * 8; Wn = Wr + (size_t)(nx - 16) * 8 * HH; }
            pa = *(const float4*)(Ap + akb);
            pw = *(const float4*)&Wn[(size_t)wr * HH + wcol];
        }
        GEMM_COMPUTE(cur)
        if (it + 1 < NT) STAGE(cur ^ 1);
    }

    // bias + per-row partial sums over this warp's 64 cols
    float s[2][2];
#pragma unroll
    for (int mt = 0; mt < 2; mt++) { s[mt][0] = 0.f; s[mt][1] = 0.f; }
#pragma unroll
    for (int mt = 0; mt < 2; mt++)
#pragma unroll
        for (int j = 0; j < 8; j++) {
            int jc = n0 + 8 * j + 2 * q;
            float2 bv = *(const float2*)&bl[jc];
            c[mt][j][0] += bv.x; c[mt][j][1] += bv.y;
            c[mt][j][2] += bv.x; c[mt][j][3] += bv.y;
            s[mt][0] += c[mt][j][0] + c[mt][j][1];
            s[mt][1] += c[mt][j][2] + c[mt][j][3];
        }
#pragma unroll
    for (int mt = 0; mt < 2; mt++) { s[mt][0] = quad_sum(s[mt][0]); s[mt][1] = quad_sum(s[mt][1]); }
    __syncthreads();   // As/Ws done; safe ordering before pbuf use
    if (q == 0) {
#pragma unroll
        for (int mt = 0; mt < 2; mt++) {
            pbuf[mrow + mt * 16 + g][nhalf] = s[mt][0];
            pbuf[mrow + mt * 16 + g + 8][nhalf] = s[mt][1];
        }
    }
    __syncthreads();
    float mu[2][2], vs[2][2];
#pragma unroll
    for (int mt = 0; mt < 2; mt++) {
        int lr0 = mrow + mt * 16 + g;
        mu[mt][0] = (pbuf[lr0][0] + pbuf[lr0][1]) * (1.f / HH);
        mu[mt][1] = (pbuf[lr0 + 8][0] + pbuf[lr0 + 8][1]) * (1.f / HH);
        vs[mt][0] = 0.f; vs[mt][1] = 0.f;
    }
#pragma unroll
    for (int mt = 0; mt < 2; mt++)
#pragma unroll
        for (int j = 0; j < 8; j++) {
            c[mt][j][0] -= mu[mt][0]; c[mt][j][1] -= mu[mt][0];
            c[mt][j][2] -= mu[mt][1]; c[mt][j][3] -= mu[mt][1];
            vs[mt][0] += c[mt][j][0] * c[mt][j][0] + c[mt][j][1] * c[mt][j][1];
            vs[mt][1] += c[mt][j][2] * c[mt][j][2] + c[mt][j][3] * c[mt][j][3];
        }
#pragma unroll
    for (int mt = 0; mt < 2; mt++) { vs[mt][0] = quad_sum(vs[mt][0]); vs[mt][1] = quad_sum(vs[mt][1]); }
    if (q == 0) {
#pragma unroll
        for (int mt = 0; mt < 2; mt++) {
            vbuf[mrow + mt * 16 + g][nhalf] = vs[mt][0];
            vbuf[mrow + mt * 16 + g + 8][nhalf] = vs[mt][1];
        }
    }
    __syncthreads();
#pragma unroll
    for (int mt = 0; mt < 2; mt++) {
        int lr0 = mrow + mt * 16 + g;
        float r0std = rsqrtf((vbuf[lr0][0] + vbuf[lr0][1]) * (1.f / HH) + 1e-5f);
        float r1std = rsqrtf((vbuf[lr0 + 8][0] + vbuf[lr0 + 8][1]) * (1.f / HH) + 1e-5f);
        int gr0 = row0 + lr0, gr1 = gr0 + 8;
#pragma unroll
        for (int j = 0; j < 8; j++) {
            int jc = n0 + 8 * j + 2 * q;
            float2 lw = *(const float2*)&lnw[jc];
            float2 lb = *(const float2*)&lnb[jc];
            float2 o0, o1;
            o0.x = c[mt][j][0] * r0std * lw.x + lb.x;
            o0.y = c[mt][j][1] * r0std * lw.y + lb.y;
            o1.x = c[mt][j][2] * r1std * lw.x + lb.x;
            o1.y = c[mt][j][3] * r1std * lw.y + lb.y;
            *(float2*)&g_h[(size_t)gr0 * HH + jc] = o0;
            *(float2*)&g_h[(size_t)gr1 * HH + jc] = o1;
        }
    }
}

// ---------------- edge MLP: gather-GEMM (K=256) + fused W2 reduction ----------------
__global__ void __launch_bounds__(NTH, 2) k_edgemlp(const int* __restrict__ eli, int Q,
        const float* __restrict__ W1, const float* __restrict__ b1,
        const float* __restrict__ W2, const float* __restrict__ b2,
        float* __restrict__ out) {
    __shared__ float As[2][128][24];
    __shared__ float Ws[2][8][264];
    __shared__ float pbuf[128][2];
    __shared__ int sbase[128], dbase[128];
    GEMM_DECLS
    const int q0 = blockIdx.x * 128;

    if (t < 128) {
        int qq = q0 + t, s = 0, d = 0;
        if (qq < Q) { s = eli[qq]; d = eli[Q + qq]; }
        sbase[t] = s * HH; dbase[t] = d * HH;
    }
    __syncthreads();
    const float* Asrc = &g_h[(size_t)sbase[ar]];
    const float* Adst = &g_h[(size_t)dbase[ar]];

    pa = *(const float4*)(Asrc + akb);
    pw = *(const float4*)&W1[(size_t)wr * HH + wcol];
    STAGE(0);

    const int NT = 32;
#pragma unroll 2
    for (int it = 0; it < NT; it++) {
        int cur = it & 1;
        __syncthreads();
        if (it + 1 < NT) {
            int nx = it + 1;
            const float* Ap = (nx < 16) ? (Asrc + nx * 8) : (Adst + (nx - 16) * 8);
            pa = *(const float4*)(Ap + akb);
            pw = *(const float4*)&W1[(size_t)(nx * 8 + wr) * HH + wcol];
        }
        GEMM_COMPUTE(cur)
        if (it + 1 < NT) STAGE(cur ^ 1);
    }

    float s[2][2];
#pragma unroll
    for (int mt = 0; mt < 2; mt++) { s[mt][0] = 0.f; s[mt][1] = 0.f; }
#pragma unroll
    for (int mt = 0; mt < 2; mt++)
#pragma unroll
        for (int j = 0; j < 8; j++) {
            int jc = n0 + 8 * j + 2 * q;
            float2 bv = *(const float2*)&b1[jc];
            float2 wv = *(const float2*)&W2[jc];
            s[mt][0] = fmaf(fmaxf(c[mt][j][0] + bv.x, 0.f), wv.x, s[mt][0]);
            s[mt][0] = fmaf(fmaxf(c[mt][j][1] + bv.y, 0.f), wv.y, s[mt][0]);
            s[mt][1] = fmaf(fmaxf(c[mt][j][2] + bv.x, 0.f), wv.x, s[mt][1]);
            s[mt][1] = fmaf(fmaxf(c[mt][j][3] + bv.y, 0.f), wv.y, s[mt][1]);
        }
#pragma unroll
    for (int mt = 0; mt < 2; mt++) { s[mt][0] = quad_sum(s[mt][0]); s[mt][1] = quad_sum(s[mt][1]); }
    __syncthreads();
    if (q == 0) {
#pragma unroll
        for (int mt = 0; mt < 2; mt++) {
            pbuf[mrow + mt * 16 + g][nhalf] = s[mt][0];
            pbuf[mrow + mt * 16 + g + 8][nhalf] = s[mt][1];
        }
    }
    __syncthreads();
    if (nhalf == 0 && q == 0) {
        float b2v = b2[0];
#pragma unroll
        for (int mt = 0; mt < 2; mt++) {
            int lr0 = mrow + mt * 16 + g;
            int q0g = q0 + lr0;
            if (q0g < Q)     out[q0g]     = pbuf[lr0][0] + pbuf[lr0][1] + b2v;
            if (q0g + 8 < Q) out[q0g + 8] = pbuf[lr0 + 8][0] + pbuf[lr0 + 8][1] + b2v;
        }
    }
}

// ---------------- host launch ----------------
extern "C" void kernel_launch(void* const* d_in, const int* in_sizes, int n_in,
                              void* d_out, int out_size) {
    const float* x    = (const float*)d_in[0];
    const int*   ei   = (const int*)d_in[1];
    const int*   eli  = (const int*)d_in[2];
    const float* p0Wp = (const float*)d_in[3];
    const float* p0bp = (const float*)d_in[4];
    const float* p0Wl = (const float*)d_in[5];
    const float* p0bl = (const float*)d_in[6];
    const float* p0Wr = (const float*)d_in[7];
    const float* Wp_s = (const float*)d_in[8];
    const float* bp_s = (const float*)d_in[9];
    const float* Wl_s = (const float*)d_in[10];
    const float* bl_s = (const float*)d_in[11];
    const float* Wr_s = (const float*)d_in[12];
    const float* ln_w = (const float*)d_in[13];
    const float* ln_b = (const float*)d_in[14];
    const float* eW1  = (const float*)d_in[15];
    const float* eb1  = (const float*)d_in[16];
    const float* eW2  = (const float*)d_in[17];
    const float* eb2  = (const float*)d_in[18];
    float* out = (float*)d_out;

    const int n = in_sizes[0] / 2;
    const int E = in_sizes[1] / 2;
    const int Q = in_sizes[2] / 2;

    // ---- CSR build (once) ----
    void* degp = nullptr;
    cudaGetSymbolAddress(&degp, g_deg);
    cudaMemsetAsync(degp, 0, (size_t)n * sizeof(int));
    k_hist<<<(E + 255) / 256, 256>>>(ei, E);
    const int nb = (n + SCAN_B - 1) / SCAN_B;
    k_scan1<<<nb, SCAN_B>>>(n);
    k_scan2<<<1, 1024>>>(nb);
    k_scan3<<<(n + 255) / 256, 256>>>(n, E);
    k_scatter<<<(E + 255) / 256, 256>>>(ei, E);

    // ---- layer 0 ----
    k_l0<<<(n + 255) / 256, 256>>>(x, p0Wp, p0bp, n);
    k_combine0<<<(n * 32 + 255) / 256, 256>>>(n, p0Wl, p0bl, p0Wr, ln_w, ln_b);

    // ---- layers 1..2 ----
    const int gb = (n + 127) / 128;   // 782
    const int gaggB = (n * 32 + 255) / 256;
    for (int l = 0; l < 2; l++) {
        k_proj<<<gb, NTH>>>(Wp_s + (size_t)l * HH * HH, bp_s + (size_t)l * HH);
        k_gagg<<<gaggB, 256>>>(n);
        k_combine<<<gb, NTH>>>(Wl_s + (size_t)l * HH * HH, Wr_s + (size_t)l * HH * HH,
                               bl_s + (size_t)l * HH,
                               ln_w + (size_t)(l + 1) * HH, ln_b + (size_t)(l + 1) * HH);
    }
    k_edgemlp<<<(Q + 127) / 128, NTH>>>(eli, Q, eW1, eb1, eW2, eb2, out);
}

// round 13
// speedup vs baseline: 1.3941x; 1.3941x over previous
#include <cuda_runtime.h>
#include <cuda_bf16.h>
#include <cstdint>

#define HH 128
#define NPAD 100096          // = 782*128
#define EMAX 1600000
#define NTH 256
#define SCAN_B 512

// ---------------- scratch ----------------
__device__ float g_xp [NPAD * HH];
__device__ float g_acc[NPAD * HH];     // MEAN-aggregated features
__device__ float g_h  [NPAD * HH];
__device__ float g_xp0[NPAD * 2];
__device__ int   g_deg [NPAD];
__device__ int   g_off [NPAD + 1];
__device__ int   g_cur [NPAD];
__device__ int   g_srcs[EMAX];
__device__ int   g_bsum [4096];
__device__ int   g_bsumx[4096];

__device__ __forceinline__ float warp_sum(float v) {
#pragma unroll
    for (int o = 16; o > 0; o >>= 1) v += __shfl_xor_sync(0xffffffffu, v, o);
    return v;
}
__device__ __forceinline__ float quad_sum(float v) {
    v += __shfl_xor_sync(0xffffffffu, v, 1);
    v += __shfl_xor_sync(0xffffffffu, v, 2);
    return v;
}
// pack two floats' bf16-hi into one u32 (low=a, high=b); lo parts in 'lo'
__device__ __forceinline__ uint32_t pack_hilo(float a, float b, uint32_t& lo) {
    __nv_bfloat16 ha = __float2bfloat16(a), hb = __float2bfloat16(b);
    float ra = a - __bfloat162float(ha), rb = b - __bfloat162float(hb);
    __nv_bfloat16 la = __float2bfloat16(ra), lb = __float2bfloat16(rb);
    lo = (uint32_t)__bfloat16_as_ushort(la) | ((uint32_t)__bfloat16_as_ushort(lb) << 16);
    return (uint32_t)__bfloat16_as_ushort(ha) | ((uint32_t)__bfloat16_as_ushort(hb) << 16);
}

#define MMA_BF16(d, a, b0v, b1v)                                                 \
    asm volatile(                                                                \
        "mma.sync.aligned.m16n8k16.row.col.f32.bf16.bf16.f32 "                   \
        "{%0,%1,%2,%3}, {%4,%5,%6,%7}, {%8,%9}, {%0,%1,%2,%3};"                  \
        : "+f"(d[0]), "+f"(d[1]), "+f"(d[2]), "+f"(d[3])                         \
        : "r"((a)[0]), "r"((a)[1]), "r"((a)[2]), "r"((a)[3]), "r"(b0v), "r"(b1v))

// ================= CSR build =================
__global__ void k_hist(const int* __restrict__ ei, int E) {
    int e = blockIdx.x * blockDim.x + threadIdx.x;
    if (e >= E) return;
    atomicAdd(&g_deg[ei[E + e]], 1);
}
__global__ void __launch_bounds__(SCAN_B) k_scan1(int n) {
    __shared__ int sm[SCAN_B];
    int t = threadIdx.x;
    int idx = blockIdx.x * SCAN_B + t;
    int v = (idx < n) ? g_deg[idx] : 0;
    sm[t] = v;
    __syncthreads();
#pragma unroll
    for (int off = 1; off < SCAN_B; off <<= 1) {
        int add = (t >= off) ? sm[t - off] : 0;
        __syncthreads();
        sm[t] += add;
        __syncthreads();
    }
    if (idx < n) g_off[idx] = sm[t] - v;
    if (t == SCAN_B - 1) g_bsum[blockIdx.x] = sm[t];
}
__global__ void __launch_bounds__(1024) k_scan2(int nb) {
    __shared__ int sm[1024];
    int t = threadIdx.x;
    int v = (t < nb) ? g_bsum[t] : 0;
    sm[t] = v;
    __syncthreads();
#pragma unroll
    for (int off = 1; off < 1024; off <<= 1) {
        int add = (t >= off) ? sm[t - off] : 0;
        __syncthreads();
        sm[t] += add;
        __syncthreads();
    }
    if (t < nb) g_bsumx[t] = sm[t] - v;
}
__global__ void k_scan3(int n, int E) {
    int idx = blockIdx.x * blockDim.x + threadIdx.x;
    if (idx == 0) g_off[n] = E;
    if (idx >= n) return;
    int o = g_off[idx] + g_bsumx[idx / SCAN_B];
    g_off[idx] = o;
    g_cur[idx] = o;
}
__global__ void k_scatter(const int* __restrict__ ei, int E) {
    int e = blockIdx.x * blockDim.x + threadIdx.x;
    if (e >= E) return;
    int s = ei[e], d = ei[E + e];
    int pos = atomicAdd(&g_cur[d], 1);
    g_srcs[pos] = s;
}

// ================= layer 0 =================
__global__ void k_l0(const float* __restrict__ x, const float* __restrict__ Wp,
                     const float* __restrict__ bp, int n) {
    int i = blockIdx.x * blockDim.x + threadIdx.x;
    if (i >= n) return;
    float x0 = x[2 * i], x1 = x[2 * i + 1];
    float a = fmaxf(fmaf(x0, Wp[0], fmaf(x1, Wp[2], bp[0])), 0.f);
    float b = fmaxf(fmaf(x0, Wp[1], fmaf(x1, Wp[3], bp[1])), 0.f);
    g_xp0[2 * i] = a;
    g_xp0[2 * i + 1] = b;
}
__global__ void __launch_bounds__(256) k_combine0(int n, const float* __restrict__ Wl,
        const float* __restrict__ bl, const float* __restrict__ Wr,
        const float* __restrict__ lnw, const float* __restrict__ lnb) {
    int node = (blockIdx.x * 256 + threadIdx.x) >> 5;
    int lane = threadIdx.x & 31;
    if (node >= n) return;
    int beg = g_off[node], end = g_off[node + 1];
    float m0 = 0.f, m1 = 0.f;
    for (int j = beg + lane; j < end; j += 32) {
        int s = __ldg(&g_srcs[j]);
        float2 v = *(const float2*)&g_xp0[2 * s];
        m0 += v.x; m1 += v.y;
    }
    m0 = warp_sum(m0); m1 = warp_sum(m1);
    float inv = 1.f / fmaxf((float)(end - beg), 1.f);
    m0 *= inv; m1 *= inv;
    float p0 = g_xp0[2 * node], p1 = g_xp0[2 * node + 1];
    float v[4]; float s = 0.f;
#pragma unroll
    for (int k = 0; k < 4; k++) {
        int c = lane + 32 * k;
        v[k] = fmaf(m0, Wl[c], fmaf(m1, Wl[HH + c],
               fmaf(p0, Wr[c], fmaf(p1, Wr[HH + c], bl[c]))));
        s += v[k];
    }
    s = warp_sum(s);
    float mu = s * (1.f / HH);
    float q = 0.f;
#pragma unroll
    for (int k = 0; k < 4; k++) { v[k] -= mu; q += v[k] * v[k]; }
    q = warp_sum(q);
    float rstd = rsqrtf(q * (1.f / HH) + 1e-5f);
    size_t base = (size_t)node * HH;
#pragma unroll
    for (int k = 0; k < 4; k++) {
        int c = lane + 32 * k;
        g_h[base + c] = v[k] * rstd * lnw[c] + lnb[c];
    }
}

// ================= aggregation: CSR gather-reduce, warp per node =================
__global__ void __launch_bounds__(256) k_gagg(int n) {
    int node = (blockIdx.x * 256 + threadIdx.x) >> 5;
    int lane = threadIdx.x & 31;
    if (node >= n) return;
    int beg = g_off[node], end = g_off[node + 1];
    float4 a0 = make_float4(0.f, 0.f, 0.f, 0.f);
    float4 a1 = make_float4(0.f, 0.f, 0.f, 0.f);
    int j = beg;
    for (; j + 4 <= end; j += 4) {
        int s0 = __ldg(&g_srcs[j]),     s1 = __ldg(&g_srcs[j + 1]);
        int s2 = __ldg(&g_srcs[j + 2]), s3 = __ldg(&g_srcs[j + 3]);
        float4 v0 = *(const float4*)&g_xp[(size_t)s0 * HH + lane * 4];
        float4 v1 = *(const float4*)&g_xp[(size_t)s1 * HH + lane * 4];
        float4 v2 = *(const float4*)&g_xp[(size_t)s2 * HH + lane * 4];
        float4 v3 = *(const float4*)&g_xp[(size_t)s3 * HH + lane * 4];
        a0.x += v0.x + v1.x; a0.y += v0.y + v1.y;
        a0.z += v0.z + v1.z; a0.w += v0.w + v1.w;
        a1.x += v2.x + v3.x; a1.y += v2.y + v3.y;
        a1.z += v2.z + v3.z; a1.w += v2.w + v3.w;
    }
    for (; j < end; j++) {
        int s0 = __ldg(&g_srcs[j]);
        float4 v0 = *(const float4*)&g_xp[(size_t)s0 * HH + lane * 4];
        a0.x += v0.x; a0.y += v0.y; a0.z += v0.z; a0.w += v0.w;
    }
    float inv = 1.f / fmaxf((float)(end - beg), 1.f);
    float4 a;
    a.x = (a0.x + a1.x) * inv; a.y = (a0.y + a1.y) * inv;
    a.z = (a0.z + a1.z) * inv; a.w = (a0.w + a1.w) * inv;
    *(float4*)&g_acc[(size_t)node * HH + lane * 4] = a;
}

// =================== 3xBF16 m16n8k16 MMA GEMM core, 4x2 warp grid ===================
// CTA tile 128x128, 8 warps as 4(M) x 2(N): warp tile 32x64. k-stage = 16.
// fp32 split once at staging into bf16 (hi,lo), packed as k-pairs:
//   As[2][128][9]  uint2 {hi,lo}: row=m, col=k2 (pair index 0..7), pad 9
//   Ws[2][8][132]  uint2 {hi,lo}: row=k2, col=n, pad 132 (conflict-free B reads)
// Per warp per k16: A = 16 LDS.64, B = 16 LDS.64, 48 MMA.m16n8k16
// (2x FLOPs/MMA and ~2x less LDS than the tf32x3 k8 core).

#define GEMM_DECLS                                                            \
    const int t = threadIdx.x;                                                \
    const int warp = t >> 5, lane = t & 31;                                   \
    const int g = lane >> 2, q = lane & 3;                                    \
    const int mrow = (warp & 3) * 32;                                         \
    const int n0 = (warp >> 2) * 64;                                          \
    const int nhalf = warp >> 2;                                              \
    const int ar = t >> 1, akb = (t & 1) * 8, ac4 = (t & 1) * 4;              \
    const int k2r = t >> 5, nb = (t & 31) * 4;                                \
    float4 pa0, pa1, pw0, pw1;                                                \
    float c[2][8][4];                                                         \
    _Pragma("unroll")                                                         \
    for (int mt = 0; mt < 2; mt++)                                            \
        _Pragma("unroll")                                                     \
        for (int j = 0; j < 8; j++)                                           \
            _Pragma("unroll")                                                 \
            for (int u = 0; u < 4; u++) c[mt][j][u] = 0.f;                    \
    (void)nhalf;

#define STAGE(buf)                                                            \
    {                                                                         \
        uint32_t lo_; uint2 e_;                                               \
        e_.x = pack_hilo(pa0.x, pa0.y, lo_); e_.y = lo_; As[buf][ar][ac4 + 0] = e_; \
        e_.x = pack_hilo(pa0.z, pa0.w, lo_); e_.y = lo_; As[buf][ar][ac4 + 1] = e_; \
        e_.x = pack_hilo(pa1.x, pa1.y, lo_); e_.y = lo_; As[buf][ar][ac4 + 2] = e_; \
        e_.x = pack_hilo(pa1.z, pa1.w, lo_); e_.y = lo_; As[buf][ar][ac4 + 3] = e_; \
        e_.x = pack_hilo(pw0.x, pw1.x, lo_); e_.y = lo_; Ws[buf][k2r][nb + 0] = e_; \
        e_.x = pack_hilo(pw0.y, pw1.y, lo_); e_.y = lo_; Ws[buf][k2r][nb + 1] = e_; \
        e_.x = pack_hilo(pw0.z, pw1.z, lo_); e_.y = lo_; Ws[buf][k2r][nb + 2] = e_; \
        e_.x = pack_hilo(pw0.w, pw1.w, lo_); e_.y = lo_; Ws[buf][k2r][nb + 3] = e_; \
    }

#define PREFETCH(Ap, Wp_)                                                     \
    {                                                                         \
        pa0 = *(const float4*)((Ap) + akb);                                   \
        pa1 = *(const float4*)((Ap) + akb + 4);                               \
        pw0 = *(const float4*)&(Wp_)[(size_t)(2 * k2r) * HH + nb];            \
        pw1 = *(const float4*)&(Wp_)[(size_t)(2 * k2r + 1) * HH + nb];        \
    }

#define GEMM_COMPUTE(cur)                                                     \
    {                                                                         \
        uint32_t ah[2][4], al[2][4];                                          \
        _Pragma("unroll")                                                     \
        for (int mt = 0; mt < 2; mt++) {                                      \
            int r = mrow + mt * 16;                                           \
            uint2 x0 = As[cur][r + g][q];                                     \
            uint2 x1 = As[cur][r + g + 8][q];                                 \
            uint2 x2 = As[cur][r + g][q + 4];                                 \
            uint2 x3 = As[cur][r + g + 8][q + 4];                             \
            ah[mt][0] = x0.x; al[mt][0] = x0.y;                               \
            ah[mt][1] = x1.x; al[mt][1] = x1.y;                               \
            ah[mt][2] = x2.x; al[mt][2] = x2.y;                               \
            ah[mt][3] = x3.x; al[mt][3] = x3.y;                               \
        }                                                                     \
        _Pragma("unroll")                                                     \
        for (int j = 0; j < 8; j++) {                                         \
            int nn = n0 + 8 * j + g;                                          \
            uint2 b0 = Ws[cur][q][nn];                                        \
            uint2 b1 = Ws[cur][q + 4][nn];                                    \
            MMA_BF16(c[0][j], ah[0], b0.y, b1.y);                             \
            MMA_BF16(c[0][j], al[0], b0.x, b1.x);                             \
            MMA_BF16(c[0][j], ah[0], b0.x, b1.x);                             \
            MMA_BF16(c[1][j], ah[1], b0.y, b1.y);                             \
            MMA_BF16(c[1][j], al[1], b0.x, b1.x);                             \
            MMA_BF16(c[1][j], ah[1], b0.x, b1.x);                             \
        }                                                                     \
    }

// ---------------- proj GEMM: xp = relu(h @ Wp + bp), K=128 ----------------
__global__ void __launch_bounds__(NTH, 2) k_proj(const float* __restrict__ W,
                                                 const float* __restrict__ bias) {
    __shared__ uint2 As[2][128][9];
    __shared__ uint2 Ws[2][8][132];
    GEMM_DECLS
    const int row0 = blockIdx.x * 128;
    const float* Arow = &g_h[(size_t)(row0 + ar) * HH];

    PREFETCH(Arow, W);
    STAGE(0);

    const int NT = HH / 16;  // 8
#pragma unroll 2
    for (int it = 0; it < NT; it++) {
        int cur = it & 1;
        __syncthreads();
        if (it + 1 < NT) {
            int k0 = (it + 1) * 16;
            PREFETCH(Arow + k0, W + (size_t)k0 * HH);
        }
        GEMM_COMPUTE(cur)
        if (it + 1 < NT) STAGE(cur ^ 1);
    }

#pragma unroll
    for (int mt = 0; mt < 2; mt++) {
        int r0 = row0 + mrow + mt * 16 + g, r1 = r0 + 8;
#pragma unroll
        for (int j = 0; j < 8; j++) {
            int jc = n0 + 8 * j + 2 * q;
            float2 bv = *(const float2*)&bias[jc];
            float2 o0, o1;
            o0.x = fmaxf(c[mt][j][0] + bv.x, 0.f); o0.y = fmaxf(c[mt][j][1] + bv.y, 0.f);
            o1.x = fmaxf(c[mt][j][2] + bv.x, 0.f); o1.y = fmaxf(c[mt][j][3] + bv.y, 0.f);
            *(float2*)&g_xp[(size_t)r0 * HH + jc] = o0;
            *(float2*)&g_xp[(size_t)r1 * HH + jc] = o1;
        }
    }
}

// ---------------- combine GEMM (K=256: mean | xp) + fused LN ----------------
__global__ void __launch_bounds__(NTH, 2) k_combine(const float* __restrict__ Wl,
        const float* __restrict__ Wr, const float* __restrict__ bl,
        const float* __restrict__ lnw, const float* __restrict__ lnb) {
    __shared__ uint2 As[2][128][9];
    __shared__ uint2 Ws[2][8][132];
    __shared__ float pbuf[128][2];
    __shared__ float vbuf[128][2];
    GEMM_DECLS
    const int row0 = blockIdx.x * 128;
    const float* Aa = &g_acc[(size_t)(row0 + ar) * HH];
    const float* Ax = &g_xp[(size_t)(row0 + ar) * HH];

    PREFETCH(Aa, Wl);
    STAGE(0);

    const int NT = 16;  // K=256 / 16
#pragma unroll 2
    for (int it = 0; it < NT; it++) {
        int cur = it & 1;
        __syncthreads();
        if (it + 1 < NT) {
            int nx = it + 1;
            const float* Ap;
            const float* Wn;
            if (nx < 8) { Ap = Aa + nx * 16; Wn = Wl + (size_t)nx * 16 * HH; }
            else        { Ap = Ax + (nx - 8) * 16; Wn = Wr + (size_t)(nx - 8) * 16 * HH; }
            PREFETCH(Ap, Wn);
        }
        GEMM_COMPUTE(cur)
        if (it + 1 < NT) STAGE(cur ^ 1);
    }

    // bias + per-row partial sums over this warp's 64 cols
    float s[2][2];
#pragma unroll
    for (int mt = 0; mt < 2; mt++) { s[mt][0] = 0.f; s[mt][1] = 0.f; }
#pragma unroll
    for (int mt = 0; mt < 2; mt++)
#pragma unroll
        for (int j = 0; j < 8; j++) {
            int jc = n0 + 8 * j + 2 * q;
            float2 bv = *(const float2*)&bl[jc];
            c[mt][j][0] += bv.x; c[mt][j][1] += bv.y;
            c[mt][j][2] += bv.x; c[mt][j][3] += bv.y;
            s[mt][0] += c[mt][j][0] + c[mt][j][1];
            s[mt][1] += c[mt][j][2] + c[mt][j][3];
        }
#pragma unroll
    for (int mt = 0; mt < 2; mt++) { s[mt][0] = quad_sum(s[mt][0]); s[mt][1] = quad_sum(s[mt][1]); }
    __syncthreads();
    if (q == 0) {
#pragma unroll
        for (int mt = 0; mt < 2; mt++) {
            pbuf[mrow + mt * 16 + g][nhalf] = s[mt][0];
            pbuf[mrow + mt * 16 + g + 8][nhalf] = s[mt][1];
        }
    }
    __syncthreads();
    float mu[2][2], vs[2][2];
#pragma unroll
    for (int mt = 0; mt < 2; mt++) {
        int lr0 = mrow + mt * 16 + g;
        mu[mt][0] = (pbuf[lr0][0] + pbuf[lr0][1]) * (1.f / HH);
        mu[mt][1] = (pbuf[lr0 + 8][0] + pbuf[lr0 + 8][1]) * (1.f / HH);
        vs[mt][0] = 0.f; vs[mt][1] = 0.f;
    }
#pragma unroll
    for (int mt = 0; mt < 2; mt++)
#pragma unroll
        for (int j = 0; j < 8; j++) {
            c[mt][j][0] -= mu[mt][0]; c[mt][j][1] -= mu[mt][0];
            c[mt][j][2] -= mu[mt][1]; c[mt][j][3] -= mu[mt][1];
            vs[mt][0] += c[mt][j][0] * c[mt][j][0] + c[mt][j][1] * c[mt][j][1];
            vs[mt][1] += c[mt][j][2] * c[mt][j][2] + c[mt][j][3] * c[mt][j][3];
        }
#pragma unroll
    for (int mt = 0; mt < 2; mt++) { vs[mt][0] = quad_sum(vs[mt][0]); vs[mt][1] = quad_sum(vs[mt][1]); }
    if (q == 0) {
#pragma unroll
        for (int mt = 0; mt < 2; mt++) {
            vbuf[mrow + mt * 16 + g][nhalf] = vs[mt][0];
            vbuf[mrow + mt * 16 + g + 8][nhalf] = vs[mt][1];
        }
    }
    __syncthreads();
#pragma unroll
    for (int mt = 0; mt < 2; mt++) {
        int lr0 = mrow + mt * 16 + g;
        float r0std = rsqrtf((vbuf[lr0][0] + vbuf[lr0][1]) * (1.f / HH) + 1e-5f);
        float r1std = rsqrtf((vbuf[lr0 + 8][0] + vbuf[lr0 + 8][1]) * (1.f / HH) + 1e-5f);
        int gr0 = row0 + lr0, gr1 = gr0 + 8;
#pragma unroll
        for (int j = 0; j < 8; j++) {
            int jc = n0 + 8 * j + 2 * q;
            float2 lw = *(const float2*)&lnw[jc];
            float2 lb = *(const float2*)&lnb[jc];
            float2 o0, o1;
            o0.x = c[mt][j][0] * r0std * lw.x + lb.x;
            o0.y = c[mt][j][1] * r0std * lw.y + lb.y;
            o1.x = c[mt][j][2] * r1std * lw.x + lb.x;
            o1.y = c[mt][j][3] * r1std * lw.y + lb.y;
            *(float2*)&g_h[(size_t)gr0 * HH + jc] = o0;
            *(float2*)&g_h[(size_t)gr1 * HH + jc] = o1;
        }
    }
}

// ---------------- edge MLP: gather-GEMM (K=256) + fused W2 reduction ----------------
__global__ void __launch_bounds__(NTH, 2) k_edgemlp(const int* __restrict__ eli, int Q,
        const float* __restrict__ W1, const float* __restrict__ b1,
        const float* __restrict__ W2, const float* __restrict__ b2,
        float* __restrict__ out) {
    __shared__ uint2 As[2][128][9];
    __shared__ uint2 Ws[2][8][132];
    __shared__ float pbuf[128][2];
    __shared__ int sbase[128], dbase[128];
    GEMM_DECLS
    const int q0 = blockIdx.x * 128;

    if (t < 128) {
        int qq = q0 + t, s = 0, d = 0;
        if (qq < Q) { s = eli[qq]; d = eli[Q + qq]; }
        sbase[t] = s * HH; dbase[t] = d * HH;
    }
    __syncthreads();
    const float* Asrc = &g_h[(size_t)sbase[ar]];
    const float* Adst = &g_h[(size_t)dbase[ar]];

    PREFETCH(Asrc, W1);
    STAGE(0);

    const int NT = 16;
#pragma unroll 2
    for (int it = 0; it < NT; it++) {
        int cur = it & 1;
        __syncthreads();
        if (it + 1 < NT) {
            int nx = it + 1;
            const float* Ap = (nx < 8) ? (Asrc + nx * 16) : (Adst + (nx - 8) * 16);
            PREFETCH(Ap, W1 + (size_t)nx * 16 * HH);
        }
        GEMM_COMPUTE(cur)
        if (it + 1 < NT) STAGE(cur ^ 1);
    }

    float s[2][2];
#pragma unroll
    for (int mt = 0; mt < 2; mt++) { s[mt][0] = 0.f; s[mt][1] = 0.f; }
#pragma unroll
    for (int mt = 0; mt < 2; mt++)
#pragma unroll
        for (int j = 0; j < 8; j++) {
            int jc = n0 + 8 * j + 2 * q;
            float2 bv = *(const float2*)&b1[jc];
            float2 wv = *(const float2*)&W2[jc];
            s[mt][0] = fmaf(fmaxf(c[mt][j][0] + bv.x, 0.f), wv.x, s[mt][0]);
            s[mt][0] = fmaf(fmaxf(c[mt][j][1] + bv.y, 0.f), wv.y, s[mt][0]);
            s[mt][1] = fmaf(fmaxf(c[mt][j][2] + bv.x, 0.f), wv.x, s[mt][1]);
            s[mt][1] = fmaf(fmaxf(c[mt][j][3] + bv.y, 0.f), wv.y, s[mt][1]);
        }
#pragma unroll
    for (int mt = 0; mt < 2; mt++) { s[mt][0] = quad_sum(s[mt][0]); s[mt][1] = quad_sum(s[mt][1]); }
    __syncthreads();
    if (q == 0) {
#pragma unroll
        for (int mt = 0; mt < 2; mt++) {
            pbuf[mrow + mt * 16 + g][nhalf] = s[mt][0];
            pbuf[mrow + mt * 16 + g + 8][nhalf] = s[mt][1];
        }
    }
    __syncthreads();
    if (nhalf == 0 && q == 0) {
        float b2v = b2[0];
#pragma unroll
        for (int mt = 0; mt < 2; mt++) {
            int lr0 = mrow + mt * 16 + g;
            int q0g = q0 + lr0;
            if (q0g < Q)     out[q0g]     = pbuf[lr0][0] + pbuf[lr0][1] + b2v;
            if (q0g + 8 < Q) out[q0g + 8] = pbuf[lr0 + 8][0] + pbuf[lr0 + 8][1] + b2v;
        }
    }
}

// ---------------- host launch ----------------
extern "C" void kernel_launch(void* const* d_in, const int* in_sizes, int n_in,
                              void* d_out, int out_size) {
    const float* x    = (const float*)d_in[0];
    const int*   ei   = (const int*)d_in[1];
    const int*   eli  = (const int*)d_in[2];
    const float* p0Wp = (const float*)d_in[3];
    const float* p0bp = (const float*)d_in[4];
    const float* p0Wl = (const float*)d_in[5];
    const float* p0bl = (const float*)d_in[6];
    const float* p0Wr = (const float*)d_in[7];
    const float* Wp_s = (const float*)d_in[8];
    const float* bp_s = (const float*)d_in[9];
    const float* Wl_s = (const float*)d_in[10];
    const float* bl_s = (const float*)d_in[11];
    const float* Wr_s = (const float*)d_in[12];
    const float* ln_w = (const float*)d_in[13];
    const float* ln_b = (const float*)d_in[14];
    const float* eW1  = (const float*)d_in[15];
    const float* eb1  = (const float*)d_in[16];
    const float* eW2  = (const float*)d_in[17];
    const float* eb2  = (const float*)d_in[18];
    float* out = (float*)d_out;

    const int n = in_sizes[0] / 2;
    const int E = in_sizes[1] / 2;
    const int Q = in_sizes[2] / 2;

    // ---- CSR build (once) ----
    void* degp = nullptr;
    cudaGetSymbolAddress(&degp, g_deg);
    cudaMemsetAsync(degp, 0, (size_t)n * sizeof(int));
    k_hist<<<(E + 255) / 256, 256>>>(ei, E);
    const int nb = (n + SCAN_B - 1) / SCAN_B;
    k_scan1<<<nb, SCAN_B>>>(n);
    k_scan2<<<1, 1024>>>(nb);
    k_scan3<<<(n + 255) / 256, 256>>>(n, E);
    k_scatter<<<(E + 255) / 256, 256>>>(ei, E);

    // ---- layer 0 ----
    k_l0<<<(n + 255) / 256, 256>>>(x, p0Wp, p0bp, n);
    k_combine0<<<(n * 32 + 255) / 256, 256>>>(n, p0Wl, p0bl, p0Wr, ln_w, ln_b);

    // ---- layers 1..2 ----
    const int gb = (n + 127) / 128;   // 782
    const int gaggB = (n * 32 + 255) / 256;
    for (int l = 0; l < 2; l++) {
        k_proj<<<gb, NTH>>>(Wp_s + (size_t)l * HH * HH, bp_s + (size_t)l * HH);
        k_gagg<<<gaggB, 256>>>(n);
        k_combine<<<gb, NTH>>>(Wl_s + (size_t)l * HH * HH, Wr_s + (size_t)l * HH * HH,
                               bl_s + (size_t)l * HH,
                               ln_w + (size_t)(l + 1) * HH, ln_b + (size_t)(l + 1) * HH);
    }
    k_edgemlp<<<(Q + 127) / 128, NTH>>>(eli, Q, eW1, eb1, eW2, eb2, out);
}